// round 13
// baseline (speedup 1.0000x reference)
#include <cuda_runtime.h>
#include <cuda_bf16.h>
#include <math.h>
#include <stdint.h>

#define N_NODES 50000
#define N_EDGES 800000
#define N_GRAPHS 64
#define F_IN 128
#define H1 512
#define H2 256
#define H3 128
#define N_CLS 10
#define BN_EPS 1e-5f
#define HMAX 512
#define SCAN_NB 49   // ceil(50000/1024)

// packed-weight segment offsets ([N][K/2] uint32 layout, contiguous)
#define W1P_OFF 0
#define W2P_OFF 32768          // 512*64
#define W3P_OFF 98304          // + 256*256
#define WP_TOTAL 114688        // + 128*128

// ------------------------ scratch (device globals; no allocs) ------------------------
__device__ float    g_deg[N_NODES];                    // dinv
__device__ int      g_counts[N_NODES];
__device__ int      g_cur[N_NODES];
__device__ int      g_bsum[64];
__device__ int      g_bbase[64];
__device__ int      g_offs[N_NODES + 1];
__device__ int2     g_csr[N_EDGES];                    // {src, norm bits} packed
__device__ uint32_t g_scr[(size_t)N_NODES * 128];      // bf16x2 scratch (aggX/agg2)
__device__ uint32_t g_h3 [(size_t)N_NODES * 64];       // bf16x2 agg3 (pool input)
__device__ uint32_t g_b16a[(size_t)N_NODES * 256];     // bf16x2 (h1, up to F=512)
__device__ uint32_t g_b16b[(size_t)N_NODES * 128];     // bf16x2 (x / h2, up to F=256)
__device__ uint32_t g_wbh[WP_TOTAL];                   // weights bf16-hi packed x2
__device__ uint32_t g_wbl[WP_TOTAL];                   // weights bf16-lo packed x2
__device__ float    g_sumf[HMAX];                      // zero-init; re-zeroed by bn_finalize
__device__ float    g_sqf [HMAX];
__device__ float    g_scale[HMAX];
__device__ float    g_shift[HMAX];
__device__ float    g_pool[N_GRAPHS * H3];
__device__ float    g_cnt [N_GRAPHS];

// ------------------------ helpers ------------------------
__device__ __forceinline__ float2 b2f(uint32_t u) {   // bf16x2 -> float2 (low = .x)
    return make_float2(__uint_as_float(u << 16), __uint_as_float(u & 0xFFFF0000u));
}

__device__ __forceinline__ uint32_t f2b2(float x, float y) {  // pack (x=low, y=high)
    __nv_bfloat162 h = __float22bfloat162_rn(make_float2(x, y));
    return *(uint32_t*)&h;
}

__device__ __forceinline__ void mma_bf16(float4& c, uint32_t a0, uint32_t a1,
                                         uint32_t a2, uint32_t a3,
                                         uint32_t b0, uint32_t b1) {
    asm volatile(
        "mma.sync.aligned.m16n8k16.row.col.f32.bf16.bf16.f32 "
        "{%0,%1,%2,%3}, {%4,%5,%6,%7}, {%8,%9}, {%0,%1,%2,%3};"
        : "+f"(c.x), "+f"(c.y), "+f"(c.z), "+f"(c.w)
        : "r"(a0), "r"(a1), "r"(a2), "r"(a3), "r"(b0), "r"(b1));
}

__device__ __forceinline__ void cp16(uint32_t dst_smem, const void* src) {
    asm volatile("cp.async.ca.shared.global [%0], [%1], 16;"
                 :: "r"(dst_smem), "l"(src));
}

// ------------------------ pre-conversions ------------------------
// All 3 weight matrices -> packed bf16 hi/lo in one launch (segments contiguous)
__global__ void conv_wp_all_kernel(const float* __restrict__ W1,
                                   const float* __restrict__ W2,
                                   const float* __restrict__ W3) {
    int idx = blockIdx.x * blockDim.x + threadIdx.x;
    if (idx >= WP_TOTAL) return;
    const float* W;
    int K, N, loc;
    if (idx < W2P_OFF)      { W = W1; K = F_IN; N = H1; loc = idx; }
    else if (idx < W3P_OFF) { W = W2; K = H1;   N = H2; loc = idx - W2P_OFF; }
    else                    { W = W3; K = H2;   N = H3; loc = idx - W3P_OFF; }
    int Kp = K >> 1;
    int n = loc / Kp, kp = loc - n * Kp;
    float w0 = W[(size_t)(2 * kp)     * N + n];
    float w1 = W[(size_t)(2 * kp + 1) * N + n];
    __nv_bfloat16 h0 = __float2bfloat16(w0);
    __nv_bfloat16 h1 = __float2bfloat16(w1);
    float l0 = w0 - __bfloat162float(h0);
    float l1 = w1 - __bfloat162float(h1);
    __nv_bfloat162 ph; ph.x = h0; ph.y = h1;
    g_wbh[idx] = *(uint32_t*)&ph;
    g_wbl[idx] = f2b2(l0, l1);
}

// x (50000x128 fp32) -> packed bf16x2 in g_b16b; also zero counters
__global__ void conv_x_kernel(const float* __restrict__ x) {
    int i = blockIdx.x * blockDim.x + threadIdx.x;
    if (i < N_NODES) { g_counts[i] = 0; g_cur[i] = 0; }
    if (i >= N_NODES * F_IN / 4) return;
    float4 v = *(const float4*)&x[i * 4];
    uint2 o;
    o.x = f2b2(v.x, v.y);
    o.y = f2b2(v.z, v.w);
    *(uint2*)&g_b16b[i * 2] = o;
}

// ------------------------ CSR construction ------------------------
__global__ void count_deg_kernel(const int* __restrict__ ei) {
    int e = blockIdx.x * blockDim.x + threadIdx.x;
    if (e < N_EDGES) atomicAdd(&g_counts[ei[N_EDGES + e]], 1);
}

// fused: dinv + per-block partial sums of counts
__global__ void partial_sum_kernel() {
    __shared__ int s[1024];
    int t = threadIdx.x;
    int i = blockIdx.x * 1024 + t;
    int c = (i < N_NODES) ? g_counts[i] : 0;
    if (i < N_NODES) g_deg[i] = rsqrtf((float)c + 1.0f);
    s[t] = c;
    __syncthreads();
    for (int st = 512; st > 0; st >>= 1) {
        if (t < st) s[t] += s[t + st];
        __syncthreads();
    }
    if (t == 0) g_bsum[blockIdx.x] = s[0];
}

__global__ void scan_bsum_kernel() {
    __shared__ int s[64];
    int t = threadIdx.x;
    int v0 = (t < SCAN_NB) ? g_bsum[t] : 0;
    s[t] = v0;
    __syncthreads();
    for (int d = 1; d < 64; d <<= 1) {
        int v = (t >= d) ? s[t - d] : 0;
        __syncthreads();
        s[t] += v;
        __syncthreads();
    }
    if (t < SCAN_NB) g_bbase[t] = s[t] - v0;   // exclusive
    if (t == 0) g_offs[N_NODES] = N_EDGES;
}

__global__ void offsets_kernel() {
    __shared__ int s[1024];
    int t = threadIdx.x;
    int i = blockIdx.x * 1024 + t;
    int c = (i < N_NODES) ? g_counts[i] : 0;
    s[t] = c;
    __syncthreads();
    for (int d = 1; d < 1024; d <<= 1) {
        int v = (t >= d) ? s[t - d] : 0;
        __syncthreads();
        s[t] += v;
        __syncthreads();
    }
    if (i < N_NODES) g_offs[i] = g_bbase[blockIdx.x] + s[t] - c;
}

__global__ void fill_csr_kernel(const int* __restrict__ ei) {
    int e = blockIdx.x * blockDim.x + threadIdx.x;
    if (e >= N_EDGES) return;
    int r = ei[e];
    int c = ei[N_EDGES + e];
    int pos = g_offs[c] + atomicAdd(&g_cur[c], 1);
    g_csr[pos] = make_int2(r, __float_as_int(g_deg[r] * g_deg[c]));
}

// ------------------------ GEMM: C = f(A) @ W  (bf16 TC, W hi+lo, A bf16) ------------------------
// 128x128 block, BK=32, 256 threads (8 warps: 2m x 4n, warp tile 64x32), double buffered,
// B tiles via cp.async, dynamic smem.
#define PSTR 20                  // uint32 row stride (16 data + 4 pad) — conflict-free frags
#define TILEU 2560               // 128 * PSTR uint32 per buffer
#define GSMEM (TILEU * 2 * 3 * 4 + HMAX * 8)   // 61440 + 4096 = 65536 bytes

template<bool APPLY_BN, bool DO_STATS>
__global__ void __launch_bounds__(256, 2)
gemm_bf16_kernel(const uint32_t* __restrict__ Ab,
                 const uint32_t* __restrict__ Bh, const uint32_t* __restrict__ Bl,
                 uint32_t* __restrict__ Cb,
                 int M, int K, int N) {
    extern __shared__ uint32_t smem[];
    uint32_t* sA  = smem;                    // [2][TILEU]
    uint32_t* sBh = smem + 2 * TILEU;        // [2][TILEU]
    uint32_t* sBl = smem + 4 * TILEU;        // [2][TILEU]
    float* sSc = (float*)(smem + 6 * TILEU);
    float* sSh = sSc + HMAX;

    int t    = threadIdx.x;
    int lane = t & 31;
    int warp = t >> 5;
    int g    = lane >> 2;      // groupID
    int tig  = lane & 3;       // threadID_in_group
    int wm   = (warp & 1) * 64;
    int wn   = (warp >> 1) * 32;
    int bm   = blockIdx.y * 128;
    int bcn  = blockIdx.x * 128;
    int Kp   = K >> 1;

    if (APPLY_BN) {
        for (int i = t; i < K; i += 256) { sSc[i] = g_scale[i]; sSh[i] = g_shift[i]; }
        __syncthreads();
    }

    // loader mappings: thread covers row (t>>1), uint32 cols (t&1)*8 .. +7 of each 16-col tile
    int am = t >> 1, ah = (t & 1) * 8;
    bool arow = (bm + am) < M;
    const uint32_t* Ap  = Ab + (size_t)(bm + am) * Kp + ah;
    const uint32_t* Bhp = Bh + (size_t)(bcn + am) * Kp + ah;
    const uint32_t* Blp = Bl + (size_t)(bcn + am) * Kp + ah;
    uint32_t smem_base = (uint32_t)__cvta_generic_to_shared(smem);
    uint32_t bdst = (am * PSTR + ah) * 4;    // byte offset within a buffer

    float4 acc[4][4];
    #pragma unroll
    for (int i = 0; i < 4; i++)
        #pragma unroll
        for (int j = 0; j < 4; j++) acc[i][j] = make_float4(0.f, 0.f, 0.f, 0.f);

    uint4 ua0, ua1;

    auto bn_fold = [&](uint4 v, int kb) -> uint4 {
        float2 p0 = b2f(v.x), p1 = b2f(v.y);
        float2 p2 = b2f(v.z), p3 = b2f(v.w);
        p0.x = fmaxf(fmaf(p0.x, sSc[kb + 0], sSh[kb + 0]), 0.f);
        p0.y = fmaxf(fmaf(p0.y, sSc[kb + 1], sSh[kb + 1]), 0.f);
        p1.x = fmaxf(fmaf(p1.x, sSc[kb + 2], sSh[kb + 2]), 0.f);
        p1.y = fmaxf(fmaf(p1.y, sSc[kb + 3], sSh[kb + 3]), 0.f);
        p2.x = fmaxf(fmaf(p2.x, sSc[kb + 4], sSh[kb + 4]), 0.f);
        p2.y = fmaxf(fmaf(p2.y, sSc[kb + 5], sSh[kb + 5]), 0.f);
        p3.x = fmaxf(fmaf(p3.x, sSc[kb + 6], sSh[kb + 6]), 0.f);
        p3.y = fmaxf(fmaf(p3.y, sSc[kb + 7], sSh[kb + 7]), 0.f);
        uint4 r;
        r.x = f2b2(p0.x, p0.y); r.y = f2b2(p1.x, p1.y);
        r.z = f2b2(p2.x, p2.y); r.w = f2b2(p3.x, p3.y);
        return r;
    };

    auto issue_B = [&](int k0, int buf) {
        uint32_t dh = smem_base + (2 * TILEU + buf * TILEU) * 4 + bdst;
        uint32_t dl = smem_base + (4 * TILEU + buf * TILEU) * 4 + bdst;
        const uint32_t* sh = Bhp + (k0 >> 1);
        const uint32_t* sl = Blp + (k0 >> 1);
        cp16(dh,      sh);
        cp16(dh + 16, sh + 4);
        cp16(dl,      sl);
        cp16(dl + 16, sl + 4);
        asm volatile("cp.async.commit_group;");
    };

    auto load_A = [&](int k0) {
        if (arow) {
            ua0 = *(const uint4*)(Ap + (k0 >> 1));
            ua1 = *(const uint4*)(Ap + (k0 >> 1) + 4);
            if (APPLY_BN) {
                int kb = k0 + ah * 2;
                ua0 = bn_fold(ua0, kb);
                ua1 = bn_fold(ua1, kb + 8);
            }
        } else {
            ua0 = make_uint4(0u, 0u, 0u, 0u);
            ua1 = ua0;
        }
    };

    auto store_A = [&](int buf) {
        *(uint4*)&sA[buf * TILEU + am * PSTR + ah]     = ua0;
        *(uint4*)&sA[buf * TILEU + am * PSTR + ah + 4] = ua1;
    };

    // prologue: tile 0
    issue_B(0, 0);
    load_A(0);
    store_A(0);
    asm volatile("cp.async.wait_group 0;" ::: "memory");
    __syncthreads();

    int buf = 0;
    for (int k0 = 0; k0 < K; k0 += 32) {
        bool more = (k0 + 32) < K;
        if (more) {
            issue_B(k0 + 32, buf ^ 1);
            load_A(k0 + 32);
        }

        int bo = buf * TILEU;
        #pragma unroll
        for (int s = 0; s < 2; s++) {
            int co = s * 8;
            uint32_t af[4][4];
            #pragma unroll
            for (int i = 0; i < 4; i++) {
                int r0 = wm + 16 * i + g;
                af[i][0] = sA[bo +  r0      * PSTR + co + tig    ];
                af[i][1] = sA[bo + (r0 + 8) * PSTR + co + tig    ];
                af[i][2] = sA[bo +  r0      * PSTR + co + tig + 4];
                af[i][3] = sA[bo + (r0 + 8) * PSTR + co + tig + 4];
            }
            #pragma unroll
            for (int j = 0; j < 4; j++) {
                int nb = wn + 8 * j + g;
                uint32_t bh0 = sBh[bo + nb * PSTR + co + tig    ];
                uint32_t bh1 = sBh[bo + nb * PSTR + co + tig + 4];
                uint32_t bl0 = sBl[bo + nb * PSTR + co + tig    ];
                uint32_t bl1 = sBl[bo + nb * PSTR + co + tig + 4];
                #pragma unroll
                for (int i = 0; i < 4; i++) {
                    mma_bf16(acc[i][j], af[i][0], af[i][1], af[i][2], af[i][3], bh0, bh1);
                    mma_bf16(acc[i][j], af[i][0], af[i][1], af[i][2], af[i][3], bl0, bl1);
                }
            }
        }

        if (more) {
            store_A(buf ^ 1);
            asm volatile("cp.async.wait_group 0;" ::: "memory");
        }
        __syncthreads();
        buf ^= 1;
    }

    // fused BN stats (exact fp32 accumulators): OOB rows contribute 0
    if (DO_STATS) {
        #pragma unroll
        for (int j = 0; j < 4; j++) {
            float sx = 0.f, sy = 0.f, qx = 0.f, qy = 0.f;
            #pragma unroll
            for (int i = 0; i < 4; i++) {
                sx += acc[i][j].x + acc[i][j].z;
                sy += acc[i][j].y + acc[i][j].w;
                qx += acc[i][j].x * acc[i][j].x + acc[i][j].z * acc[i][j].z;
                qy += acc[i][j].y * acc[i][j].y + acc[i][j].w * acc[i][j].w;
            }
            #pragma unroll
            for (int m = 4; m < 32; m <<= 1) {
                sx += __shfl_xor_sync(0xffffffffu, sx, m);
                sy += __shfl_xor_sync(0xffffffffu, sy, m);
                qx += __shfl_xor_sync(0xffffffffu, qx, m);
                qy += __shfl_xor_sync(0xffffffffu, qy, m);
            }
            if (lane < 4) {
                int n = bcn + wn + 8 * j + 2 * lane;
                atomicAdd(&g_sumf[n],     sx);
                atomicAdd(&g_sumf[n + 1], sy);
                atomicAdd(&g_sqf [n],     qx);
                atomicAdd(&g_sqf [n + 1], qy);
            }
        }
    }

    // epilogue: bf16 packed store
    #pragma unroll
    for (int i = 0; i < 4; i++) {
        int m0 = bm + wm + 16 * i + g;
        int m1 = m0 + 8;
        #pragma unroll
        for (int j = 0; j < 4; j++) {
            int n = bcn + wn + 8 * j + 2 * tig;
            if (m0 < M) Cb[((size_t)m0 * N + n) >> 1] = f2b2(acc[i][j].x, acc[i][j].y);
            if (m1 < M) Cb[((size_t)m1 * N + n) >> 1] = f2b2(acc[i][j].z, acc[i][j].w);
        }
    }
}

// ------------------------ CSR gather, F=128 (lane: 4 feats, uint2), unroll-8 ------------------------
template<bool DO_STATS>
__global__ void gather_bf16_kernel(const uint32_t* __restrict__ src,
                                   uint32_t* __restrict__ dst, int F) {
    __shared__ float s_ps[8][128];
    __shared__ float s_pq[8][128];

    int t    = threadIdx.x;
    int lane = t & 31;
    int w    = t >> 5;
    int node = blockIdx.x * 8 + w;          // 50000 = 6250*8
    int f0   = lane * 4;
    int Fu   = F >> 1;
    int f0u  = (f0 >> 1);

    float di = g_deg[node];
    float sl = di * di;
    uint2 sv = *(const uint2*)&src[(size_t)node * Fu + f0u];
    float2 sa = b2f(sv.x), sb = b2f(sv.y);
    float4 acc = make_float4(sa.x * sl, sa.y * sl, sb.x * sl, sb.y * sl);

    int j   = g_offs[node];
    int end = g_offs[node + 1];
    for (; j + 8 <= end; j += 8) {
        int2  e[8];
        uint2 u[8];
        #pragma unroll
        for (int q = 0; q < 8; q++) e[q] = g_csr[j + q];
        #pragma unroll
        for (int q = 0; q < 8; q++)
            u[q] = *(const uint2*)&src[(size_t)e[q].x * Fu + f0u];
        #pragma unroll
        for (int q = 0; q < 8; q++) {
            float nq = __int_as_float(e[q].y);
            float2 aq = b2f(u[q].x), bq = b2f(u[q].y);
            acc.x = fmaf(aq.x, nq, acc.x); acc.y = fmaf(aq.y, nq, acc.y);
            acc.z = fmaf(bq.x, nq, acc.z); acc.w = fmaf(bq.y, nq, acc.w);
        }
    }
    for (; j < end; j++) {
        int2 e0 = g_csr[j];
        float n0 = __int_as_float(e0.y);
        uint2 u0 = *(const uint2*)&src[(size_t)e0.x * Fu + f0u];
        float2 a0 = b2f(u0.x), b0 = b2f(u0.y);
        acc.x = fmaf(a0.x, n0, acc.x); acc.y = fmaf(a0.y, n0, acc.y);
        acc.z = fmaf(b0.x, n0, acc.z); acc.w = fmaf(b0.y, n0, acc.w);
    }
    uint2 outv;
    outv.x = f2b2(acc.x, acc.y);
    outv.y = f2b2(acc.z, acc.w);
    *(uint2*)&dst[(size_t)node * Fu + f0u] = outv;

    if (DO_STATS) {
        *(float4*)&s_ps[w][lane * 4] = acc;
        *(float4*)&s_pq[w][lane * 4] = make_float4(acc.x * acc.x, acc.y * acc.y,
                                                   acc.z * acc.z, acc.w * acc.w);
        __syncthreads();
        if (t < 128) {
            float s = 0.f;
            #pragma unroll
            for (int ww = 0; ww < 8; ww++) s += s_ps[ww][t];
            atomicAdd(&g_sumf[t], s);
        } else {
            int t2 = t - 128;
            float s = 0.f;
            #pragma unroll
            for (int ww = 0; ww < 8; ww++) s += s_pq[ww][t2];
            atomicAdd(&g_sqf[t2], s);
        }
    }
}

// ------------------------ CSR gather, F=256 single pass (lane: 8 feats, uint4), unroll-4 ------------------------
template<bool DO_STATS>
__global__ void gather256_kernel(const uint32_t* __restrict__ src,
                                 uint32_t* __restrict__ dst) {
    __shared__ float s_ps[8][256];
    __shared__ float s_pq[8][256];

    const int Fu = 128;                     // 256 feats = 128 uint32
    int t    = threadIdx.x;
    int lane = t & 31;
    int w    = t >> 5;
    int node = blockIdx.x * 8 + w;
    int f0u  = lane * 4;

    float di = g_deg[node];
    float sl = di * di;
    uint4 sv = *(const uint4*)&src[(size_t)node * Fu + f0u];
    float2 s0 = b2f(sv.x), s1 = b2f(sv.y), s2 = b2f(sv.z), s3 = b2f(sv.w);
    float acc[8] = {s0.x * sl, s0.y * sl, s1.x * sl, s1.y * sl,
                    s2.x * sl, s2.y * sl, s3.x * sl, s3.y * sl};

    int j   = g_offs[node];
    int end = g_offs[node + 1];
    for (; j + 4 <= end; j += 4) {
        int2  e[4];
        uint4 u[4];
        #pragma unroll
        for (int q = 0; q < 4; q++) e[q] = g_csr[j + q];
        #pragma unroll
        for (int q = 0; q < 4; q++)
            u[q] = *(const uint4*)&src[(size_t)e[q].x * Fu + f0u];
        #pragma unroll
        for (int q = 0; q < 4; q++) {
            float nq = __int_as_float(e[q].y);
            float2 a0 = b2f(u[q].x), a1 = b2f(u[q].y), a2 = b2f(u[q].z), a3 = b2f(u[q].w);
            acc[0] = fmaf(a0.x, nq, acc[0]); acc[1] = fmaf(a0.y, nq, acc[1]);
            acc[2] = fmaf(a1.x, nq, acc[2]); acc[3] = fmaf(a1.y, nq, acc[3]);
            acc[4] = fmaf(a2.x, nq, acc[4]); acc[5] = fmaf(a2.y, nq, acc[5]);
            acc[6] = fmaf(a3.x, nq, acc[6]); acc[7] = fmaf(a3.y, nq, acc[7]);
        }
    }
    for (; j < end; j++) {
        int2 e0 = g_csr[j];
        float n0 = __int_as_float(e0.y);
        uint4 u0 = *(const uint4*)&src[(size_t)e0.x * Fu + f0u];
        float2 a0 = b2f(u0.x), a1 = b2f(u0.y), a2 = b2f(u0.z), a3 = b2f(u0.w);
        acc[0] = fmaf(a0.x, n0, acc[0]); acc[1] = fmaf(a0.y, n0, acc[1]);
        acc[2] = fmaf(a1.x, n0, acc[2]); acc[3] = fmaf(a1.y, n0, acc[3]);
        acc[4] = fmaf(a2.x, n0, acc[4]); acc[5] = fmaf(a2.y, n0, acc[5]);
        acc[6] = fmaf(a3.x, n0, acc[6]); acc[7] = fmaf(a3.y, n0, acc[7]);
    }
    uint4 outv;
    outv.x = f2b2(acc[0], acc[1]);
    outv.y = f2b2(acc[2], acc[3]);
    outv.z = f2b2(acc[4], acc[5]);
    outv.w = f2b2(acc[6], acc[7]);
    *(uint4*)&dst[(size_t)node * Fu + f0u] = outv;

    if (DO_STATS) {
        #pragma unroll
        for (int i = 0; i < 8; i++) {
            s_ps[w][lane * 8 + i] = acc[i];
            s_pq[w][lane * 8 + i] = acc[i] * acc[i];
        }
        __syncthreads();
        float s = 0.f, q = 0.f;
        #pragma unroll
        for (int ww = 0; ww < 8; ww++) { s += s_ps[ww][t]; q += s_pq[ww][t]; }
        atomicAdd(&g_sumf[t], s);
        atomicAdd(&g_sqf[t], q);
    }
}

// compute scale/shift, then re-zero the accumulators for the next use/replay
template<bool ZERO_POOL>
__global__ void bn_finalize_kernel(const float* __restrict__ gamma,
                                   const float* __restrict__ beta) {
    int f = threadIdx.x;
    double mean = (double)g_sumf[f] * (1.0 / N_NODES);
    double var  = (double)g_sqf[f] * (1.0 / N_NODES) - mean * mean;
    float scale = gamma[f] * rsqrtf((float)var + BN_EPS);
    g_scale[f] = scale;
    g_shift[f] = beta[f] - (float)mean * scale;
    g_sumf[f] = 0.f;
    g_sqf[f]  = 0.f;
    if (ZERO_POOL) {
        for (int i = f; i < N_GRAPHS * H3; i += H3) g_pool[i] = 0.f;
        if (f < N_GRAPHS) g_cnt[f] = 0.f;
    }
}

// ------------------------ pool (fused BN3+ReLU, run-length atomics; bf16 input) ------------------------
__global__ void pool_kernel(const int* __restrict__ batch) {
    int f  = threadIdx.x;
    int n0 = blockIdx.x * 32;
    int ne = min(n0 + 32, N_NODES);
    float sc = g_scale[f], sh = g_shift[f];
    const __nv_bfloat16* h3 = (const __nv_bfloat16*)g_h3;
    int curg = batch[n0];
    float run = 0.f, cnt = 0.f;
    for (int n = n0; n < ne; n++) {
        int g = batch[n];
        if (g != curg) {
            atomicAdd(&g_pool[curg * H3 + f], run);
            if (f == 0) atomicAdd(&g_cnt[curg], cnt);
            run = 0.f; cnt = 0.f; curg = g;
        }
        float v = __bfloat162float(h3[(size_t)n * H3 + f]);
        run += fmaxf(fmaf(v, sc, sh), 0.f);
        cnt += 1.f;
    }
    atomicAdd(&g_pool[curg * H3 + f], run);
    if (f == 0) atomicAdd(&g_cnt[curg], cnt);
}

__global__ void final_linear_kernel(const float* __restrict__ Wo,
                                    const float* __restrict__ bo,
                                    float* __restrict__ out) {
    int t = blockIdx.x * blockDim.x + threadIdx.x;
    if (t >= N_GRAPHS * N_CLS) return;
    int g = t / N_CLS;
    int c = t % N_CLS;
    float inv_cnt = 1.0f / fmaxf(g_cnt[g], 1.0f);
    float s = 0.0f;
    #pragma unroll 8
    for (int f = 0; f < H3; f++)
        s += g_pool[g * H3 + f] * Wo[f * N_CLS + c];
    out[t] = s * inv_cnt + bo[c];
}

// ------------------------ host orchestration ------------------------
extern "C" void kernel_launch(void* const* d_in, const int* in_sizes, int n_in,
                              void* d_out, int out_size) {
    const float* x     = (const float*)d_in[0];
    const int*   ei    = (const int*)d_in[1];
    const int*   batch = (const int*)d_in[2];
    const float* W1 = (const float*)d_in[3];
    const float* g1 = (const float*)d_in[5];
    const float* be1 = (const float*)d_in[6];
    const float* W2 = (const float*)d_in[7];
    const float* g2 = (const float*)d_in[9];
    const float* be2 = (const float*)d_in[10];
    const float* W3 = (const float*)d_in[11];
    const float* g3 = (const float*)d_in[13];
    const float* be3 = (const float*)d_in[14];
    const float* Wo = (const float*)d_in[15];
    const float* bo = (const float*)d_in[16];
    float* out = (float*)d_out;

    void *scrp = nullptr, *h3p = nullptr, *ap = nullptr, *bp = nullptr, *whp = nullptr, *wlp = nullptr;
    cudaGetSymbolAddress(&scrp, g_scr);
    cudaGetSymbolAddress(&h3p, g_h3);
    cudaGetSymbolAddress(&ap, g_b16a);
    cudaGetSymbolAddress(&bp, g_b16b);
    cudaGetSymbolAddress(&whp, g_wbh);
    cudaGetSymbolAddress(&wlp, g_wbl);
    uint32_t* scr  = (uint32_t*)scrp;   // aggX (F=128) then agg2 (F=256)
    uint32_t* h3b  = (uint32_t*)h3p;    // agg3 (F=128)
    uint32_t* b16a = (uint32_t*)ap;     // h1 (F=512), then h3 (F=128)
    uint32_t* b16b = (uint32_t*)bp;     // x (F=128), then h2 (F=256)
    uint32_t* wh   = (uint32_t*)whp;
    uint32_t* wl   = (uint32_t*)wlp;

    // allow 64KB dynamic smem on both GEMM instantiations (idempotent)
    static bool attr_done = false;
    if (!attr_done) {
        cudaFuncSetAttribute(gemm_bf16_kernel<false, true>,
                             cudaFuncAttributeMaxDynamicSharedMemorySize, GSMEM);
        cudaFuncSetAttribute(gemm_bf16_kernel<true, false>,
                             cudaFuncAttributeMaxDynamicSharedMemorySize, GSMEM);
        attr_done = true;
    }

    // pre-conversions (conv_x also zeros counters); one launch for all weights
    conv_x_kernel<<<(N_NODES * F_IN / 4 + 255) / 256, 256>>>(x);
    conv_wp_all_kernel<<<(WP_TOTAL + 255) / 256, 256>>>(W1, W2, W3);

    // CSR build (by target) + dinv
    count_deg_kernel<<<(N_EDGES + 255) / 256, 256>>>(ei);
    partial_sum_kernel<<<SCAN_NB, 1024>>>();
    scan_bsum_kernel<<<1, 64>>>();
    offsets_kernel<<<SCAN_NB, 1024>>>();
    fill_csr_kernel<<<(N_EDGES + 255) / 256, 256>>>(ei);

    const int MB = (N_NODES + 127) / 128;   // 391

    // layer 1: aggX = A_hat x -> scr ; h1 = aggX @ W1 -> b16a (fused exact stats)
    gather_bf16_kernel<false><<<N_NODES / 8, 256>>>(b16b, scr, F_IN);
    gemm_bf16_kernel<false, true><<<dim3(H1 / 128, MB), 256, GSMEM>>>(
        scr, wh + W1P_OFF, wl + W1P_OFF, b16a, N_NODES, F_IN, H1);
    bn_finalize_kernel<false><<<1, H1>>>(g1, be1);

    // layer 2: h2 = relu(bn(h1)) @ W2 -> b16b ; agg2 = A_hat h2 -> scr (single-pass, +stats)
    gemm_bf16_kernel<true, false><<<dim3(H2 / 128, MB), 256, GSMEM>>>(
        b16a, wh + W2P_OFF, wl + W2P_OFF, b16b, N_NODES, H1, H2);
    gather256_kernel<true><<<N_NODES / 8, 256>>>(b16b, scr);
    bn_finalize_kernel<false><<<1, H2>>>(g2, be2);

    // layer 3: h3 = relu(bn(agg2)) @ W3 -> b16a ; agg3 = A_hat h3 -> g_h3 (+stats)
    gemm_bf16_kernel<true, false><<<dim3(H3 / 128, MB), 256, GSMEM>>>(
        scr, wh + W3P_OFF, wl + W3P_OFF, b16a, N_NODES, H2, H3);
    gather_bf16_kernel<true><<<N_NODES / 8, 256>>>(b16a, h3b, H3);
    bn_finalize_kernel<true><<<1, H3>>>(g3, be3);   // also zeros pool

    // pool (BN3+ReLU fused) + output head
    pool_kernel<<<(N_NODES + 31) / 32, 128>>>(batch);
    final_linear_kernel<<<(N_GRAPHS * N_CLS + 255) / 256, 256>>>(Wo, bo, out);
}

// round 14
// speedup vs baseline: 1.0381x; 1.0381x over previous
#include <cuda_runtime.h>
#include <cuda_bf16.h>
#include <math.h>
#include <stdint.h>

#define N_NODES 50000
#define N_EDGES 800000
#define N_GRAPHS 64
#define F_IN 128
#define H1 512
#define H2 256
#define H3 128
#define N_CLS 10
#define BN_EPS 1e-5f
#define HMAX 512
#define SCAN_NB 49   // ceil(50000/1024)

// packed-weight segment offsets ([N][K/2] uint32 layout, contiguous)
#define W1P_OFF 0
#define W2P_OFF 32768          // 512*64
#define W3P_OFF 98304          // + 256*256
#define WP_TOTAL 114688        // + 128*128

// ------------------------ scratch (device globals; no allocs) ------------------------
// g_counts / g_cur are zero on load and re-zeroed at the END of each call (pool_kernel).
__device__ float    g_deg[N_NODES];                    // dinv
__device__ int      g_counts[N_NODES];
__device__ int      g_cur[N_NODES];
__device__ int      g_bsum[64];
__device__ int      g_bbase[64];
__device__ int      g_offs[N_NODES + 1];
__device__ int2     g_csr[N_EDGES];                    // {src, norm bits} packed
__device__ uint32_t g_scr[(size_t)N_NODES * 128];      // bf16x2 scratch (aggX/agg2)
__device__ uint32_t g_h3 [(size_t)N_NODES * 64];       // bf16x2 agg3 (pool input)
__device__ uint32_t g_b16a[(size_t)N_NODES * 256];     // bf16x2 (h1, up to F=512)
__device__ uint32_t g_b16b[(size_t)N_NODES * 128];     // bf16x2 (x / h2, up to F=256)
__device__ uint32_t g_wbh[WP_TOTAL];                   // weights bf16-hi packed x2
__device__ uint32_t g_wbl[WP_TOTAL];                   // weights bf16-lo packed x2
__device__ float    g_sumf[HMAX];                      // zero-init; re-zeroed by bn_finalize
__device__ float    g_sqf [HMAX];
__device__ float    g_scale[HMAX];
__device__ float    g_shift[HMAX];
__device__ float    g_pool[N_GRAPHS * H3];
__device__ float    g_cnt [N_GRAPHS];

// ------------------------ helpers ------------------------
__device__ __forceinline__ float2 b2f(uint32_t u) {   // bf16x2 -> float2 (low = .x)
    return make_float2(__uint_as_float(u << 16), __uint_as_float(u & 0xFFFF0000u));
}

__device__ __forceinline__ uint32_t f2b2(float x, float y) {  // pack (x=low, y=high)
    __nv_bfloat162 h = __float22bfloat162_rn(make_float2(x, y));
    return *(uint32_t*)&h;
}

__device__ __forceinline__ void mma_bf16(float4& c, uint32_t a0, uint32_t a1,
                                         uint32_t a2, uint32_t a3,
                                         uint32_t b0, uint32_t b1) {
    asm volatile(
        "mma.sync.aligned.m16n8k16.row.col.f32.bf16.bf16.f32 "
        "{%0,%1,%2,%3}, {%4,%5,%6,%7}, {%8,%9}, {%0,%1,%2,%3};"
        : "+f"(c.x), "+f"(c.y), "+f"(c.z), "+f"(c.w)
        : "r"(a0), "r"(a1), "r"(a2), "r"(a3), "r"(b0), "r"(b1));
}

// ------------------------ fused setup: x->bf16, degree count, weight conversion ------------------------
// grid covers N_NODES*F_IN/4 = 1.6M threads; sub-ranges also count edges / convert weights.
// Requires g_counts == 0 on entry (guaranteed: zero-init at load; re-zeroed by pool_kernel).
__global__ void setup_kernel(const float* __restrict__ x, const int* __restrict__ ei,
                             const float* __restrict__ W1, const float* __restrict__ W2,
                             const float* __restrict__ W3) {
    int i = blockIdx.x * blockDim.x + threadIdx.x;

    // x conversion (all 1.6M threads)
    if (i < N_NODES * F_IN / 4) {
        float4 v = *(const float4*)&x[i * 4];
        uint2 o;
        o.x = f2b2(v.x, v.y);
        o.y = f2b2(v.z, v.w);
        *(uint2*)&g_b16b[i * 2] = o;
    }

    // degree counting (first 800k threads)
    if (i < N_EDGES) atomicAdd(&g_counts[ei[N_EDGES + i]], 1);

    // weight hi/lo conversion (first 114688 threads)
    if (i < WP_TOTAL) {
        const float* W;
        int K, N, loc;
        if (i < W2P_OFF)      { W = W1; K = F_IN; N = H1; loc = i; }
        else if (i < W3P_OFF) { W = W2; K = H1;   N = H2; loc = i - W2P_OFF; }
        else                  { W = W3; K = H2;   N = H3; loc = i - W3P_OFF; }
        int Kp = K >> 1;
        int n = loc / Kp, kp = loc - n * Kp;
        float w0 = W[(size_t)(2 * kp)     * N + n];
        float w1 = W[(size_t)(2 * kp + 1) * N + n];
        __nv_bfloat16 h0 = __float2bfloat16(w0);
        __nv_bfloat16 h1 = __float2bfloat16(w1);
        float l0 = w0 - __bfloat162float(h0);
        float l1 = w1 - __bfloat162float(h1);
        __nv_bfloat162 ph; ph.x = h0; ph.y = h1;
        g_wbh[i] = *(uint32_t*)&ph;
        g_wbl[i] = f2b2(l0, l1);
    }
}

// ------------------------ CSR construction ------------------------
// fused: dinv + per-block partial sums of counts
__global__ void partial_sum_kernel() {
    __shared__ int s[1024];
    int t = threadIdx.x;
    int i = blockIdx.x * 1024 + t;
    int c = (i < N_NODES) ? g_counts[i] : 0;
    if (i < N_NODES) g_deg[i] = rsqrtf((float)c + 1.0f);
    s[t] = c;
    __syncthreads();
    for (int st = 512; st > 0; st >>= 1) {
        if (t < st) s[t] += s[t + st];
        __syncthreads();
    }
    if (t == 0) g_bsum[blockIdx.x] = s[0];
}

__global__ void scan_bsum_kernel() {
    __shared__ int s[64];
    int t = threadIdx.x;
    int v0 = (t < SCAN_NB) ? g_bsum[t] : 0;
    s[t] = v0;
    __syncthreads();
    for (int d = 1; d < 64; d <<= 1) {
        int v = (t >= d) ? s[t - d] : 0;
        __syncthreads();
        s[t] += v;
        __syncthreads();
    }
    if (t < SCAN_NB) g_bbase[t] = s[t] - v0;   // exclusive
    if (t == 0) g_offs[N_NODES] = N_EDGES;
}

__global__ void offsets_kernel() {
    __shared__ int s[1024];
    int t = threadIdx.x;
    int i = blockIdx.x * 1024 + t;
    int c = (i < N_NODES) ? g_counts[i] : 0;
    s[t] = c;
    __syncthreads();
    for (int d = 1; d < 1024; d <<= 1) {
        int v = (t >= d) ? s[t - d] : 0;
        __syncthreads();
        s[t] += v;
        __syncthreads();
    }
    if (i < N_NODES) g_offs[i] = g_bbase[blockIdx.x] + s[t] - c;
}

__global__ void fill_csr_kernel(const int* __restrict__ ei) {
    int e = blockIdx.x * blockDim.x + threadIdx.x;
    if (e >= N_EDGES) return;
    int r = ei[e];
    int c = ei[N_EDGES + e];
    int pos = g_offs[c] + atomicAdd(&g_cur[c], 1);
    g_csr[pos] = make_int2(r, __float_as_int(g_deg[r] * g_deg[c]));
}

// ------------------------ GEMM: C = f(A) @ W  (bf16 TC, W hi+lo, A bf16) ------------------------
// 128x128 block, BK=16, 256 threads (8 warps: 2m x 4n, warp tile 64x32), double buffered.
#define PSTR 12

template<bool APPLY_BN, bool DO_STATS>
__global__ void __launch_bounds__(256, 2)
gemm_bf16_kernel(const uint32_t* __restrict__ Ab,
                 const uint32_t* __restrict__ Bh, const uint32_t* __restrict__ Bl,
                 uint32_t* __restrict__ Cb,
                 int M, int K, int N) {
    __shared__ uint32_t sA [2][128 * PSTR];
    __shared__ uint32_t sBh[2][128 * PSTR];
    __shared__ uint32_t sBl[2][128 * PSTR];
    __shared__ float sSc[HMAX], sSh[HMAX];

    int t    = threadIdx.x;
    int lane = t & 31;
    int warp = t >> 5;
    int g    = lane >> 2;      // groupID
    int tig  = lane & 3;       // threadID_in_group
    int wm   = (warp & 1) * 64;
    int wn   = (warp >> 1) * 32;
    int bm   = blockIdx.y * 128;
    int bcn  = blockIdx.x * 128;
    int Kp   = K >> 1;

    if (APPLY_BN) {
        for (int i = t; i < K; i += 256) { sSc[i] = g_scale[i]; sSh[i] = g_shift[i]; }
        __syncthreads();
    }

    // loader mappings
    int am = t >> 1, ak = (t & 1) * 8;
    bool arow = (bm + am) < M;
    const uint32_t* Ap = Ab + (size_t)(bm + am) * Kp + (t & 1) * 4;
    int bnr = t >> 1, bq = (t & 1) * 4;
    const uint32_t* Bhp = Bh + (size_t)(bcn + bnr) * Kp + bq;
    const uint32_t* Blp = Bl + (size_t)(bcn + bnr) * Kp + bq;

    float4 acc[4][4];
    #pragma unroll
    for (int i = 0; i < 4; i++)
        #pragma unroll
        for (int j = 0; j < 4; j++) acc[i][j] = make_float4(0.f, 0.f, 0.f, 0.f);

    uint4 ua, ubh, ubl;

    auto load_tile = [&](int k0) {
        if (arow) {
            uint4 raw = *(const uint4*)(Ap + (k0 >> 1));
            if (APPLY_BN) {
                int kb = k0 + ak;
                float2 p0 = b2f(raw.x), p1 = b2f(raw.y);
                float2 p2 = b2f(raw.z), p3 = b2f(raw.w);
                p0.x = fmaxf(fmaf(p0.x, sSc[kb + 0], sSh[kb + 0]), 0.f);
                p0.y = fmaxf(fmaf(p0.y, sSc[kb + 1], sSh[kb + 1]), 0.f);
                p1.x = fmaxf(fmaf(p1.x, sSc[kb + 2], sSh[kb + 2]), 0.f);
                p1.y = fmaxf(fmaf(p1.y, sSc[kb + 3], sSh[kb + 3]), 0.f);
                p2.x = fmaxf(fmaf(p2.x, sSc[kb + 4], sSh[kb + 4]), 0.f);
                p2.y = fmaxf(fmaf(p2.y, sSc[kb + 5], sSh[kb + 5]), 0.f);
                p3.x = fmaxf(fmaf(p3.x, sSc[kb + 6], sSh[kb + 6]), 0.f);
                p3.y = fmaxf(fmaf(p3.y, sSc[kb + 7], sSh[kb + 7]), 0.f);
                ua.x = f2b2(p0.x, p0.y); ua.y = f2b2(p1.x, p1.y);
                ua.z = f2b2(p2.x, p2.y); ua.w = f2b2(p3.x, p3.y);
            } else {
                ua = raw;
            }
        } else {
            ua = make_uint4(0u, 0u, 0u, 0u);
        }
        ubh = *(const uint4*)(Bhp + (k0 >> 1));
        ubl = *(const uint4*)(Blp + (k0 >> 1));
    };

    auto store_tile = [&](int buf) {
        *(uint4*)&sA [buf][am  * PSTR + (t & 1) * 4] = ua;
        *(uint4*)&sBh[buf][bnr * PSTR + bq]          = ubh;
        *(uint4*)&sBl[buf][bnr * PSTR + bq]          = ubl;
    };

    load_tile(0);
    store_tile(0);
    __syncthreads();

    int buf = 0;
    for (int k0 = 0; k0 < K; k0 += 16) {
        bool more = (k0 + 16) < K;
        if (more) load_tile(k0 + 16);

        uint32_t af[4][4];
        #pragma unroll
        for (int i = 0; i < 4; i++) {
            int r0 = wm + 16 * i + g;
            af[i][0] = sA[buf][ r0      * PSTR + tig    ];
            af[i][1] = sA[buf][(r0 + 8) * PSTR + tig    ];
            af[i][2] = sA[buf][ r0      * PSTR + tig + 4];
            af[i][3] = sA[buf][(r0 + 8) * PSTR + tig + 4];
        }
        #pragma unroll
        for (int j = 0; j < 4; j++) {
            int nb = wn + 8 * j + g;
            uint32_t bh0 = sBh[buf][nb * PSTR + tig    ];
            uint32_t bh1 = sBh[buf][nb * PSTR + tig + 4];
            uint32_t bl0 = sBl[buf][nb * PSTR + tig    ];
            uint32_t bl1 = sBl[buf][nb * PSTR + tig + 4];
            #pragma unroll
            for (int i = 0; i < 4; i++) {
                mma_bf16(acc[i][j], af[i][0], af[i][1], af[i][2], af[i][3], bh0, bh1);
                mma_bf16(acc[i][j], af[i][0], af[i][1], af[i][2], af[i][3], bl0, bl1);
            }
        }

        if (more) store_tile(buf ^ 1);
        __syncthreads();
        buf ^= 1;
    }

    // fused BN stats (exact fp32 accumulators): OOB rows contribute 0
    if (DO_STATS) {
        #pragma unroll
        for (int j = 0; j < 4; j++) {
            float sx = 0.f, sy = 0.f, qx = 0.f, qy = 0.f;
            #pragma unroll
            for (int i = 0; i < 4; i++) {
                sx += acc[i][j].x + acc[i][j].z;
                sy += acc[i][j].y + acc[i][j].w;
                qx += acc[i][j].x * acc[i][j].x + acc[i][j].z * acc[i][j].z;
                qy += acc[i][j].y * acc[i][j].y + acc[i][j].w * acc[i][j].w;
            }
            #pragma unroll
            for (int m = 4; m < 32; m <<= 1) {
                sx += __shfl_xor_sync(0xffffffffu, sx, m);
                sy += __shfl_xor_sync(0xffffffffu, sy, m);
                qx += __shfl_xor_sync(0xffffffffu, qx, m);
                qy += __shfl_xor_sync(0xffffffffu, qy, m);
            }
            if (lane < 4) {
                int n = bcn + wn + 8 * j + 2 * lane;
                atomicAdd(&g_sumf[n],     sx);
                atomicAdd(&g_sumf[n + 1], sy);
                atomicAdd(&g_sqf [n],     qx);
                atomicAdd(&g_sqf [n + 1], qy);
            }
        }
    }

    // epilogue: bf16 packed store
    #pragma unroll
    for (int i = 0; i < 4; i++) {
        int m0 = bm + wm + 16 * i + g;
        int m1 = m0 + 8;
        #pragma unroll
        for (int j = 0; j < 4; j++) {
            int n = bcn + wn + 8 * j + 2 * tig;
            if (m0 < M) Cb[((size_t)m0 * N + n) >> 1] = f2b2(acc[i][j].x, acc[i][j].y);
            if (m1 < M) Cb[((size_t)m1 * N + n) >> 1] = f2b2(acc[i][j].z, acc[i][j].w);
        }
    }
}

// ------------------------ CSR gather, F=128 (lane: 4 feats, uint2), unroll-8 ------------------------
template<bool DO_STATS>
__global__ void gather_bf16_kernel(const uint32_t* __restrict__ src,
                                   uint32_t* __restrict__ dst, int F) {
    __shared__ float s_ps[8][128];
    __shared__ float s_pq[8][128];

    int t    = threadIdx.x;
    int lane = t & 31;
    int w    = t >> 5;
    int node = blockIdx.x * 8 + w;          // 50000 = 6250*8
    int f0   = lane * 4;
    int Fu   = F >> 1;
    int f0u  = (f0 >> 1);

    float di = g_deg[node];
    float sl = di * di;
    uint2 sv = *(const uint2*)&src[(size_t)node * Fu + f0u];
    float2 sa = b2f(sv.x), sb = b2f(sv.y);
    float4 acc = make_float4(sa.x * sl, sa.y * sl, sb.x * sl, sb.y * sl);

    int j   = g_offs[node];
    int end = g_offs[node + 1];
    for (; j + 8 <= end; j += 8) {
        int2  e[8];
        uint2 u[8];
        #pragma unroll
        for (int q = 0; q < 8; q++) e[q] = g_csr[j + q];
        #pragma unroll
        for (int q = 0; q < 8; q++)
            u[q] = *(const uint2*)&src[(size_t)e[q].x * Fu + f0u];
        #pragma unroll
        for (int q = 0; q < 8; q++) {
            float nq = __int_as_float(e[q].y);
            float2 aq = b2f(u[q].x), bq = b2f(u[q].y);
            acc.x = fmaf(aq.x, nq, acc.x); acc.y = fmaf(aq.y, nq, acc.y);
            acc.z = fmaf(bq.x, nq, acc.z); acc.w = fmaf(bq.y, nq, acc.w);
        }
    }
    for (; j < end; j++) {
        int2 e0 = g_csr[j];
        float n0 = __int_as_float(e0.y);
        uint2 u0 = *(const uint2*)&src[(size_t)e0.x * Fu + f0u];
        float2 a0 = b2f(u0.x), b0 = b2f(u0.y);
        acc.x = fmaf(a0.x, n0, acc.x); acc.y = fmaf(a0.y, n0, acc.y);
        acc.z = fmaf(b0.x, n0, acc.z); acc.w = fmaf(b0.y, n0, acc.w);
    }
    uint2 outv;
    outv.x = f2b2(acc.x, acc.y);
    outv.y = f2b2(acc.z, acc.w);
    *(uint2*)&dst[(size_t)node * Fu + f0u] = outv;

    if (DO_STATS) {
        *(float4*)&s_ps[w][lane * 4] = acc;
        *(float4*)&s_pq[w][lane * 4] = make_float4(acc.x * acc.x, acc.y * acc.y,
                                                   acc.z * acc.z, acc.w * acc.w);
        __syncthreads();
        if (t < 128) {
            float s = 0.f;
            #pragma unroll
            for (int ww = 0; ww < 8; ww++) s += s_ps[ww][t];
            atomicAdd(&g_sumf[t], s);
        } else {
            int t2 = t - 128;
            float s = 0.f;
            #pragma unroll
            for (int ww = 0; ww < 8; ww++) s += s_pq[ww][t2];
            atomicAdd(&g_sqf[t2], s);
        }
    }
}

// ------------------------ CSR gather, F=256 single pass (lane: 8 feats, uint4), unroll-4 ------------------------
template<bool DO_STATS>
__global__ void gather256_kernel(const uint32_t* __restrict__ src,
                                 uint32_t* __restrict__ dst) {
    __shared__ float s_ps[8][256];
    __shared__ float s_pq[8][256];

    const int Fu = 128;                     // 256 feats = 128 uint32
    int t    = threadIdx.x;
    int lane = t & 31;
    int w    = t >> 5;
    int node = blockIdx.x * 8 + w;
    int f0u  = lane * 4;

    float di = g_deg[node];
    float sl = di * di;
    uint4 sv = *(const uint4*)&src[(size_t)node * Fu + f0u];
    float2 s0 = b2f(sv.x), s1 = b2f(sv.y), s2 = b2f(sv.z), s3 = b2f(sv.w);
    float acc[8] = {s0.x * sl, s0.y * sl, s1.x * sl, s1.y * sl,
                    s2.x * sl, s2.y * sl, s3.x * sl, s3.y * sl};

    int j   = g_offs[node];
    int end = g_offs[node + 1];
    for (; j + 4 <= end; j += 4) {
        int2  e[4];
        uint4 u[4];
        #pragma unroll
        for (int q = 0; q < 4; q++) e[q] = g_csr[j + q];
        #pragma unroll
        for (int q = 0; q < 4; q++)
            u[q] = *(const uint4*)&src[(size_t)e[q].x * Fu + f0u];
        #pragma unroll
        for (int q = 0; q < 4; q++) {
            float nq = __int_as_float(e[q].y);
            float2 a0 = b2f(u[q].x), a1 = b2f(u[q].y), a2 = b2f(u[q].z), a3 = b2f(u[q].w);
            acc[0] = fmaf(a0.x, nq, acc[0]); acc[1] = fmaf(a0.y, nq, acc[1]);
            acc[2] = fmaf(a1.x, nq, acc[2]); acc[3] = fmaf(a1.y, nq, acc[3]);
            acc[4] = fmaf(a2.x, nq, acc[4]); acc[5] = fmaf(a2.y, nq, acc[5]);
            acc[6] = fmaf(a3.x, nq, acc[6]); acc[7] = fmaf(a3.y, nq, acc[7]);
        }
    }
    for (; j < end; j++) {
        int2 e0 = g_csr[j];
        float n0 = __int_as_float(e0.y);
        uint4 u0 = *(const uint4*)&src[(size_t)e0.x * Fu + f0u];
        float2 a0 = b2f(u0.x), a1 = b2f(u0.y), a2 = b2f(u0.z), a3 = b2f(u0.w);
        acc[0] = fmaf(a0.x, n0, acc[0]); acc[1] = fmaf(a0.y, n0, acc[1]);
        acc[2] = fmaf(a1.x, n0, acc[2]); acc[3] = fmaf(a1.y, n0, acc[3]);
        acc[4] = fmaf(a2.x, n0, acc[4]); acc[5] = fmaf(a2.y, n0, acc[5]);
        acc[6] = fmaf(a3.x, n0, acc[6]); acc[7] = fmaf(a3.y, n0, acc[7]);
    }
    uint4 outv;
    outv.x = f2b2(acc[0], acc[1]);
    outv.y = f2b2(acc[2], acc[3]);
    outv.z = f2b2(acc[4], acc[5]);
    outv.w = f2b2(acc[6], acc[7]);
    *(uint4*)&dst[(size_t)node * Fu + f0u] = outv;

    if (DO_STATS) {
        #pragma unroll
        for (int i = 0; i < 8; i++) {
            s_ps[w][lane * 8 + i] = acc[i];
            s_pq[w][lane * 8 + i] = acc[i] * acc[i];
        }
        __syncthreads();
        float s = 0.f, q = 0.f;
        #pragma unroll
        for (int ww = 0; ww < 8; ww++) { s += s_ps[ww][t]; q += s_pq[ww][t]; }
        atomicAdd(&g_sumf[t], s);
        atomicAdd(&g_sqf[t], q);
    }
}

// compute scale/shift, then re-zero the accumulators for the next use/replay
template<bool ZERO_POOL>
__global__ void bn_finalize_kernel(const float* __restrict__ gamma,
                                   const float* __restrict__ beta) {
    int f = threadIdx.x;
    double mean = (double)g_sumf[f] * (1.0 / N_NODES);
    double var  = (double)g_sqf[f] * (1.0 / N_NODES) - mean * mean;
    float scale = gamma[f] * rsqrtf((float)var + BN_EPS);
    g_scale[f] = scale;
    g_shift[f] = beta[f] - (float)mean * scale;
    g_sumf[f] = 0.f;
    g_sqf[f]  = 0.f;
    if (ZERO_POOL) {
        for (int i = f; i < N_GRAPHS * H3; i += H3) g_pool[i] = 0.f;
        if (f < N_GRAPHS) g_cnt[f] = 0.f;
    }
}

// ------------------------ pool (fused BN3+ReLU, run-length atomics; bf16 input) ------------------------
// also re-zeroes g_counts/g_cur for the next call/replay (setup_kernel requires it)
__global__ void pool_kernel(const int* __restrict__ batch) {
    int gid = blockIdx.x * blockDim.x + threadIdx.x;
    if (gid < N_NODES) { g_counts[gid] = 0; g_cur[gid] = 0; }

    int f  = threadIdx.x;
    int n0 = blockIdx.x * 32;
    int ne = min(n0 + 32, N_NODES);
    float sc = g_scale[f], sh = g_shift[f];
    const __nv_bfloat16* h3 = (const __nv_bfloat16*)g_h3;
    int curg = batch[n0];
    float run = 0.f, cnt = 0.f;
    for (int n = n0; n < ne; n++) {
        int g = batch[n];
        if (g != curg) {
            atomicAdd(&g_pool[curg * H3 + f], run);
            if (f == 0) atomicAdd(&g_cnt[curg], cnt);
            run = 0.f; cnt = 0.f; curg = g;
        }
        float v = __bfloat162float(h3[(size_t)n * H3 + f]);
        run += fmaxf(fmaf(v, sc, sh), 0.f);
        cnt += 1.f;
    }
    atomicAdd(&g_pool[curg * H3 + f], run);
    if (f == 0) atomicAdd(&g_cnt[curg], cnt);
}

__global__ void final_linear_kernel(const float* __restrict__ Wo,
                                    const float* __restrict__ bo,
                                    float* __restrict__ out) {
    int t = blockIdx.x * blockDim.x + threadIdx.x;
    if (t >= N_GRAPHS * N_CLS) return;
    int g = t / N_CLS;
    int c = t % N_CLS;
    float inv_cnt = 1.0f / fmaxf(g_cnt[g], 1.0f);
    float s = 0.0f;
    #pragma unroll 8
    for (int f = 0; f < H3; f++)
        s += g_pool[g * H3 + f] * Wo[f * N_CLS + c];
    out[t] = s * inv_cnt + bo[c];
}

// ------------------------ host orchestration ------------------------
extern "C" void kernel_launch(void* const* d_in, const int* in_sizes, int n_in,
                              void* d_out, int out_size) {
    const float* x     = (const float*)d_in[0];
    const int*   ei    = (const int*)d_in[1];
    const int*   batch = (const int*)d_in[2];
    const float* W1 = (const float*)d_in[3];
    const float* g1 = (const float*)d_in[5];
    const float* be1 = (const float*)d_in[6];
    const float* W2 = (const float*)d_in[7];
    const float* g2 = (const float*)d_in[9];
    const float* be2 = (const float*)d_in[10];
    const float* W3 = (const float*)d_in[11];
    const float* g3 = (const float*)d_in[13];
    const float* be3 = (const float*)d_in[14];
    const float* Wo = (const float*)d_in[15];
    const float* bo = (const float*)d_in[16];
    float* out = (float*)d_out;

    void *scrp = nullptr, *h3p = nullptr, *ap = nullptr, *bp = nullptr, *whp = nullptr, *wlp = nullptr;
    cudaGetSymbolAddress(&scrp, g_scr);
    cudaGetSymbolAddress(&h3p, g_h3);
    cudaGetSymbolAddress(&ap, g_b16a);
    cudaGetSymbolAddress(&bp, g_b16b);
    cudaGetSymbolAddress(&whp, g_wbh);
    cudaGetSymbolAddress(&wlp, g_wbl);
    uint32_t* scr  = (uint32_t*)scrp;   // aggX (F=128) then agg2 (F=256)
    uint32_t* h3b  = (uint32_t*)h3p;    // agg3 (F=128)
    uint32_t* b16a = (uint32_t*)ap;     // h1 (F=512), then h3 (F=128)
    uint32_t* b16b = (uint32_t*)bp;     // x (F=128), then h2 (F=256)
    uint32_t* wh   = (uint32_t*)whp;
    uint32_t* wl   = (uint32_t*)wlp;

    // fused setup: x->bf16 + degree count + weight conversion (counters pre-zeroed)
    setup_kernel<<<(N_NODES * F_IN / 4 + 255) / 256, 256>>>(x, ei, W1, W2, W3);

    // CSR build (by target) + dinv
    partial_sum_kernel<<<SCAN_NB, 1024>>>();
    scan_bsum_kernel<<<1, 64>>>();
    offsets_kernel<<<SCAN_NB, 1024>>>();
    fill_csr_kernel<<<(N_EDGES + 255) / 256, 256>>>(ei);

    const int MB = (N_NODES + 127) / 128;   // 391

    // layer 1: aggX = A_hat x -> scr ; h1 = aggX @ W1 -> b16a (fused exact stats)
    gather_bf16_kernel<false><<<N_NODES / 8, 256>>>(b16b, scr, F_IN);
    gemm_bf16_kernel<false, true><<<dim3(H1 / 128, MB), 256>>>(
        scr, wh + W1P_OFF, wl + W1P_OFF, b16a, N_NODES, F_IN, H1);
    bn_finalize_kernel<false><<<1, H1>>>(g1, be1);

    // layer 2: h2 = relu(bn(h1)) @ W2 -> b16b ; agg2 = A_hat h2 -> scr (single-pass, +stats)
    gemm_bf16_kernel<true, false><<<dim3(H2 / 128, MB), 256>>>(
        b16a, wh + W2P_OFF, wl + W2P_OFF, b16b, N_NODES, H1, H2);
    gather256_kernel<true><<<N_NODES / 8, 256>>>(b16b, scr);
    bn_finalize_kernel<false><<<1, H2>>>(g2, be2);

    // layer 3: h3 = relu(bn(agg2)) @ W3 -> b16a ; agg3 = A_hat h3 -> g_h3 (+stats)
    gemm_bf16_kernel<true, false><<<dim3(H3 / 128, MB), 256>>>(
        scr, wh + W3P_OFF, wl + W3P_OFF, b16a, N_NODES, H2, H3);
    gather_bf16_kernel<true><<<N_NODES / 8, 256>>>(b16a, h3b, H3);
    bn_finalize_kernel<true><<<1, H3>>>(g3, be3);   // also zeros pool

    // pool (BN3+ReLU fused; also re-zeroes counters for next call) + output head
    pool_kernel<<<(N_NODES + 31) / 32, 128>>>(batch);
    final_linear_kernel<<<(N_GRAPHS * N_CLS + 255) / 256, 256>>>(Wo, bo, out);
}